// round 6
// baseline (speedup 1.0000x reference)
#include <cuda_runtime.h>
#include <cstdint>

// Problem constants (fixed shapes from the reference)
constexpr int T = 8;
constexpr int N = 200000;
constexpr int D = 128;        // embedding dim (fp32) -> 512 bytes/row
constexpr int B = 8192;       // bags per table (power of 2)
constexpr int L = 163840;     // indices per table
constexpr int D4 = D / 4;     // 32 float4 per row; one per lane
constexpr int UNROLL = 8;     // rows in flight per warp (cp.async depth)
constexpr int WARPS_PER_CTA = 2;

constexpr int TOTAL_BAGS   = T * B;          // 65536
constexpr int NUM_STREAMS  = 32;             // distributed work queues
constexpr int CHUNK        = 64;             // bags per chunk (interleave grain)
constexpr int BAGS_PER_STREAM = TOTAL_BAGS / NUM_STREAMS;   // 2048
constexpr int CHUNKS_PER_STREAM = BAGS_PER_STREAM / CHUNK;  // 32

// One padded counter per stream (own 128B line: no false sharing in L2).
struct __align__(128) StreamCtr { unsigned int v; unsigned int pad[31]; };
__device__ StreamCtr g_ctr[NUM_STREAMS];

__global__ void reset_counters_kernel() {
    if (threadIdx.x < NUM_STREAMS) g_ctr[threadIdx.x].v = 0u;
}

__device__ __forceinline__ uint32_t smem_u32(const void* p) {
    uint32_t a;
    asm("{ .reg .u64 t; cvta.to.shared.u64 t, %1; cvt.u32.u64 %0, t; }"
        : "=r"(a) : "l"(p));
    return a;
}

// Predicated 16-byte async copy gmem -> smem (no register destination:
// MLP=8 coexists with 32 regs/thread).
__device__ __forceinline__ void cp_async16(uint32_t saddr, const void* gptr, int pred) {
    asm volatile(
        "{\n\t"
        ".reg .pred p;\n\t"
        "setp.ne.u32 p, %2, 0;\n\t"
        "@p cp.async.cg.shared.global [%0], [%1], 16;\n\t"
        "}"
        :: "r"(saddr), "l"(gptr), "r"((unsigned)pred) : "memory");
}

// Persistent wave. Each warp repeatedly grabs ONE bag from its stream's
// counter (zero skew idling). Streams are 64-bag-chunk interleavings of the
// global bag order, so all streams sweep the same table region together and
// the L2 active window stays ~one table wide (preserves duplicate-row reuse).
__global__ __launch_bounds__(WARPS_PER_CTA * 32)
void grouped_embedding_bag_kernel(const float* __restrict__ weights,   // [T, N, D]
                                  const int*   __restrict__ values,    // [T, L]
                                  const int*   __restrict__ offsets,   // [T, B+1]
                                  float*       __restrict__ out)       // [B, T*D]
{
    __shared__ float4 buf[WARPS_PER_CTA][UNROLL][32];   // 8 KB per CTA

    const int lane    = threadIdx.x & 31;
    const int warp_in = threadIdx.x >> 5;
    const int stream  = blockIdx.x & (NUM_STREAMS - 1);

    const uint32_t s_base = smem_u32(&buf[warp_in][0][lane]);
    float4* __restrict__ out4 = reinterpret_cast<float4*>(out);

    while (true) {
        // Grab one bag from my stream.
        unsigned int pos;
        if (lane == 0) pos = atomicAdd(&g_ctr[stream].v, 1u);
        pos = __shfl_sync(0xffffffffu, pos, 0);
        if (pos >= (unsigned)BAGS_PER_STREAM) return;

        // Decode stream position -> global bag id (chunk interleave).
        const int chunk_in_stream = (int)(pos >> 6);        // / CHUNK
        const int off_in_chunk    = (int)(pos & (CHUNK - 1));
        const int g  = ((chunk_in_stream * NUM_STREAMS + stream) << 6) + off_in_chunk;
        const int t  = g >> 13;          // / B  (B = 8192 = 2^13)
        const int b  = g & (B - 1);      // % B

        const int start = __ldg(&offsets[t * (B + 1) + b]);
        const int end   = __ldg(&offsets[t * (B + 1) + b + 1]);

        const float4* __restrict__ wt =
            reinterpret_cast<const float4*>(weights) + (size_t)t * N * D4;
        const int* __restrict__ vals = values + (size_t)t * L;

        float acc0 = 0.f, acc1 = 0.f, acc2 = 0.f, acc3 = 0.f;

        // Prime: indices for the first batch.
        int idx[UNROLL];
        #pragma unroll
        for (int j = 0; j < UNROLL; ++j)
            idx[j] = (start + j < end) ? __ldg(&vals[start + j]) : -1;

        for (int i = start; i < end; i += UNROLL) {
            // Issue the 8 row gathers for this batch (predicated on validity).
            #pragma unroll
            for (int j = 0; j < UNROLL; ++j) {
                const float4* gp = wt + (size_t)(idx[j] < 0 ? 0 : idx[j]) * D4 + lane;
                cp_async16(s_base + (uint32_t)(j * 32 * sizeof(float4)), gp, idx[j] >= 0);
            }
            asm volatile("cp.async.commit_group;" ::: "memory");

            // Prefetch next batch's indices while the copies are in flight.
            const int ni = i + UNROLL;
            int nidx[UNROLL];
            #pragma unroll
            for (int j = 0; j < UNROLL; ++j)
                nidx[j] = (ni + j < end) ? __ldg(&vals[ni + j]) : -1;

            asm volatile("cp.async.wait_group 0;" ::: "memory");

            // Accumulate (self-written smem slice: no syncwarp needed).
            #pragma unroll
            for (int j = 0; j < UNROLL; ++j) {
                if (idx[j] >= 0) {
                    float4 v = buf[warp_in][j][lane];
                    acc0 += v.x; acc1 += v.y; acc2 += v.z; acc3 += v.w;
                }
            }

            #pragma unroll
            for (int j = 0; j < UNROLL; ++j) idx[j] = nidx[j];
        }

        // out[b, t*D + lane*4 .. +4) — streaming store, never re-read.
        __stcs(out4 + (size_t)b * (T * D4) + t * D4 + lane,
               make_float4(acc0, acc1, acc2, acc3));
    }
}

extern "C" void kernel_launch(void* const* d_in, const int* in_sizes, int n_in,
                              void* d_out, int out_size)
{
    const float* weights = (const float*)d_in[0];   // [T, N, D] fp32
    const int*   values  = (const int*)d_in[1];     // [T, L] int32
    const int*   offsets = (const int*)d_in[2];     // [T, B+1] int32
    float*       out     = (float*)d_out;           // [B, T*D] fp32

    reset_counters_kernel<<<1, NUM_STREAMS>>>();

    // One persistent wave: 28 CTAs/SM (8KB smem each, 228KB/SM) x 152 SMs.
    const int threads = WARPS_PER_CTA * 32;   // 64
    const int blocks  = 152 * 28;             // 4256

    grouped_embedding_bag_kernel<<<blocks, threads>>>(weights, values, offsets, out);
}

// round 7
// speedup vs baseline: 1.0608x; 1.0608x over previous
#include <cuda_runtime.h>
#include <cstdint>

// Problem constants (fixed shapes from the reference)
constexpr int T = 8;
constexpr int N = 200000;
constexpr int D = 128;        // embedding dim (fp32) -> 512 bytes/row
constexpr int B = 8192;       // bags per table (power of 2)
constexpr int L = 163840;     // indices per table
constexpr int D4 = D / 4;     // 32 float4 per row; one per lane

constexpr int GROUP = 4;      // rows per cp.async group
constexpr int RING  = 4;      // smem group slots per warp (3 committed ahead)
constexpr int WARPS_PER_CTA = 2;

constexpr int TOTAL_BAGS      = T * B;                       // 65536
constexpr int NUM_STREAMS     = 32;
constexpr int BAGS_PER_STREAM = TOTAL_BAGS / NUM_STREAMS;    // 2048

// One padded counter per stream (own 128B line).
struct __align__(128) StreamCtr { unsigned int v; unsigned int pad[31]; };
__device__ StreamCtr g_ctr[NUM_STREAMS];

__global__ void reset_counters_kernel() {
    if (threadIdx.x < NUM_STREAMS) g_ctr[threadIdx.x].v = 0u;
}

__device__ __forceinline__ uint32_t smem_u32(const void* p) {
    uint32_t a;
    asm("{ .reg .u64 t; cvta.to.shared.u64 t, %1; cvt.u32.u64 %0, t; }"
        : "=r"(a) : "l"(p));
    return a;
}

__device__ __forceinline__ void cp_async16(uint32_t saddr, const void* gptr, int pred) {
    asm volatile(
        "{\n\t"
        ".reg .pred p;\n\t"
        "setp.ne.u32 p, %2, 0;\n\t"
        "@p cp.async.cg.shared.global [%0], [%1], 16;\n\t"
        "}"
        :: "r"(saddr), "l"(gptr), "r"((unsigned)pred) : "memory");
}

// Continuous-stream gather: issue side walks bags (prefetched one ahead,
// atomic grab hidden); accumulate side trails 3 groups behind. The cp.async
// pipeline never drains -> gather duty ~100% (R6 showed DRAM% == duty cycle).
// meta pack: [g:17 | count:3 | last:1] -> (g<<4)|(count<<1)|last
__global__ __launch_bounds__(WARPS_PER_CTA * 32)
void grouped_embedding_bag_kernel(const float* __restrict__ weights,   // [T, N, D]
                                  const int*   __restrict__ values,    // [T, L]
                                  const int*   __restrict__ offsets,   // [T, B+1]
                                  float*       __restrict__ out)       // [B, T*D]
{
    __shared__ float4 buf[WARPS_PER_CTA][RING * GROUP][32];   // 16 KB per CTA

    const int lane    = threadIdx.x & 31;
    const int warp_in = threadIdx.x >> 5;
    const int stream  = blockIdx.x & (NUM_STREAMS - 1);

    const uint32_t s_base = smem_u32(&buf[warp_in][0][lane]);
    const float4* __restrict__ w4 = reinterpret_cast<const float4*>(weights);
    float4* __restrict__ out4 = reinterpret_cast<float4*>(out);

    // ---- bag fetch (warp-collective; one bag of lookahead) ----
    // current bag state
    int  cg = 0, ci = 0, cend = 0; bool chave = false;
    // next bag state
    int  ng = 0, ni = 0, nend = 0; bool nhave = false;

    auto fetch_into = [&](int& g, int& i, int& e, bool& have) {
        unsigned int pos;
        if (lane == 0) pos = atomicAdd(&g_ctr[stream].v, 1u);
        pos = __shfl_sync(0xffffffffu, pos, 0);
        if (pos >= (unsigned)BAGS_PER_STREAM) { have = false; return; }
        const int chunk = (int)(pos >> 6);
        const int off   = (int)(pos & 63);
        g = ((chunk * NUM_STREAMS + stream) << 6) + off;
        const int t = g >> 13;
        const int b = g & (B - 1);
        i = __ldg(&offsets[t * (B + 1) + b]);
        e = __ldg(&offsets[t * (B + 1) + b + 1]);
        have = true;
    };

    fetch_into(cg, ci, cend, chave);
    fetch_into(ng, ni, nend, nhave);

    // ---- issue one group into smem slot; returns meta ----
    auto issue_one = [&](int slot) -> unsigned int {
        unsigned int m = 0u;
        if (chave) {
            const int t = cg >> 13;
            const int* __restrict__ vals = values + (size_t)t * L;
            const float4* __restrict__ wt = w4 + (size_t)t * N * D4;
            const int count = min(GROUP, cend - ci);
            const bool last = (ci + count >= cend);
            #pragma unroll
            for (int j = 0; j < GROUP; ++j) {
                const int valid = (j < count);
                const int idx = valid ? __ldg(&vals[ci + j]) : 0;
                cp_async16(s_base + (uint32_t)((slot * GROUP + j) * 32 * sizeof(float4)),
                           wt + (size_t)idx * D4 + lane, valid);
            }
            m = ((unsigned)cg << 4) | ((unsigned)count << 1) | (last ? 1u : 0u);
            ci += count;
            if (last) {
                // advance to prefetched bag; refill lookahead (atomic hidden)
                cg = ng; ci = ni; cend = nend; chave = nhave;
                fetch_into(ng, ni, nend, nhave);
            }
        }
        asm volatile("cp.async.commit_group;" ::: "memory");
        return m;
    };

    float acc0 = 0.f, acc1 = 0.f, acc2 = 0.f, acc3 = 0.f;

    auto accumulate = [&](unsigned int m, int slot) {
        const int count = (int)((m >> 1) & 7u);
        #pragma unroll
        for (int j = 0; j < GROUP; ++j) {
            if (j < count) {
                float4 v = buf[warp_in][slot * GROUP + j][lane];
                acc0 += v.x; acc1 += v.y; acc2 += v.z; acc3 += v.w;
            }
        }
        if (m & 1u) {   // last group of its bag: flush
            const int g = (int)(m >> 4);
            const int t = g >> 13;
            const int b = g & (B - 1);
            __stcs(out4 + (size_t)b * (T * D4) + t * D4 + lane,
                   make_float4(acc0, acc1, acc2, acc3));
            acc0 = acc1 = acc2 = acc3 = 0.f;
        }
    };

    // ---- prime: 3 groups committed ahead ----
    unsigned int meta_a = issue_one(0);
    unsigned int meta_b = issue_one(1);
    unsigned int meta_c = issue_one(2);
    int s_acc = 0, s_issue = 3;

    while (true) {
        asm volatile("cp.async.wait_group 2;" ::: "memory");   // oldest done
        accumulate(meta_a, s_acc);
        s_acc = (s_acc + 1) & (RING - 1);
        if (chave) {
            const unsigned int m = issue_one(s_issue);
            s_issue = (s_issue + 1) & (RING - 1);
            meta_a = meta_b; meta_b = meta_c; meta_c = m;
        } else {
            // drain the remaining two pending groups
            asm volatile("cp.async.wait_group 1;" ::: "memory");
            accumulate(meta_b, s_acc);
            s_acc = (s_acc + 1) & (RING - 1);
            asm volatile("cp.async.wait_group 0;" ::: "memory");
            accumulate(meta_c, s_acc);
            break;
        }
    }
}

extern "C" void kernel_launch(void* const* d_in, const int* in_sizes, int n_in,
                              void* d_out, int out_size)
{
    const float* weights = (const float*)d_in[0];   // [T, N, D] fp32
    const int*   values  = (const int*)d_in[1];     // [T, L] int32
    const int*   offsets = (const int*)d_in[2];     // [T, B+1] int32
    float*       out     = (float*)d_out;           // [B, T*D] fp32

    reset_counters_kernel<<<1, NUM_STREAMS>>>();

    // One persistent wave: 14 CTAs/SM (16KB smem each) x 152 SMs.
    const int threads = WARPS_PER_CTA * 32;   // 64
    const int blocks  = 152 * 14;             // 2128

    grouped_embedding_bag_kernel<<<blocks, threads>>>(weights, values, offsets, out);
}